// round 17
// baseline (speedup 1.0000x reference)
#include <cuda_runtime.h>
#include <cuda_bf16.h>
#include <float.h>
#include <cstdint>

// Problem constants (fixed by the dataset)
#define MAX_NODES 100000
#define MAX_TOTAL 1703936   // E + n upper bound
#define D_FEAT 32
#define D_HID 64
#define D_OUT 64
#define TILE_E 64
#define H_STRIDE 68   // floats per H row (64 + pad, 16B-aligned)

// Scratch: per-node precomputed terms.
// U[j] = x_j @ W1[:32] + pos_j @ W1[32:35] + b1   (N x 64)
// P[i] = pos_i @ W1[32:35]                        (N x 64)
__device__ float g_U[MAX_NODES * D_HID];
__device__ float g_P[MAX_NODES * D_HID];
// Normalized edge list (int32, self-loops appended): size total = E + n.
__device__ __align__(16) int g_SRC[MAX_TOTAL];
__device__ __align__(16) int g_DST[MAX_TOTAL];

// ---------------------------------------------------------------------------
// packed fp32x2 helpers (each is exactly two independent .rn fp32 ops)
// ---------------------------------------------------------------------------
__device__ __forceinline__ void ffma2(unsigned long long& d,
                                      unsigned long long a,
                                      unsigned long long b) {
    asm("fma.rn.f32x2 %0, %1, %2, %0;" : "+l"(d) : "l"(a), "l"(b));
}
__device__ __forceinline__ unsigned long long mul2(unsigned long long a,
                                                   unsigned long long b) {
    unsigned long long r;
    asm("mul.rn.f32x2 %0, %1, %2;" : "=l"(r) : "l"(a), "l"(b));
    return r;
}
__device__ __forceinline__ unsigned long long add2(unsigned long long a,
                                                   unsigned long long b) {
    unsigned long long r;
    asm("add.rn.f32x2 %0, %1, %2;" : "=l"(r) : "l"(a), "l"(b));
    return r;
}
__device__ __forceinline__ unsigned long long packdup(float x) {
    unsigned long long r;
    asm("mov.b64 %0, {%1, %1};" : "=l"(r) : "f"(x));
    return r;
}
__device__ __forceinline__ unsigned long long pack2f(float a, float b) {
    unsigned long long r;
    asm("mov.b64 %0, {%1, %2};" : "=l"(r) : "f"(a), "f"(b));
    return r;
}
__device__ __forceinline__ void unpack2(unsigned long long v, float& lo, float& hi) {
    asm("mov.b64 {%0, %1}, %2;" : "=f"(lo), "=f"(hi) : "l"(v));
}
__device__ __forceinline__ void prefetchL2(const void* p) {
    asm volatile("prefetch.global.L2 [%0];" :: "l"(p));
}

// ---------------------------------------------------------------------------
// Kernel 1: fused setup — per-block dtype detect + edge normalize (int4-
// vectorized fast path) + U/P precompute (4 outputs/thread, packed f32x2;
// bit-exact chains) + out init.
// ---------------------------------------------------------------------------
__global__ void setup_kernel(const void* __restrict__ ei_raw,
                             const float* __restrict__ x,
                             const float* __restrict__ pos,
                             const float* __restrict__ W1,
                             const float* __restrict__ b1,
                             float* __restrict__ out,
                             int E, int n) {
    __shared__ float W1s[35 * 64];
    __shared__ float b1s[64];
    __shared__ int s_is64;

    if (threadIdx.x == 0) s_is64 = 1;
    for (int i = threadIdx.x; i < 35 * 64; i += blockDim.x) W1s[i] = W1[i];
    if (threadIdx.x < 64) b1s[threadIdx.x] = b1[threadIdx.x];
    __syncthreads();
    // ---- Block-local dtype detection (int32 data read as int64 lands out
    // of [0,n) with ~certainty over 256 samples). ----
    {
        const long long* ei64 = (const long long*)ei_raw;
        int samples = min(256, E);
        int bad = 0;
        for (int i = threadIdx.x; i < samples; i += blockDim.x) {
            long long v = ei64[i];
            if (v < 0 || v >= (long long)n) bad = 1;
        }
        if (__syncthreads_or(bad)) {
            if (threadIdx.x == 0) s_is64 = 0;
        }
        __syncthreads();
    }
    const int is64 = s_is64;

    const int gidx = blockIdx.x * blockDim.x + threadIdx.x;
    const int gstride = gridDim.x * blockDim.x;
    const int total = E + n;

    // ---- Loop A: normalize edge list (int32, self-loops appended) ----
    if (!is64 && (E & 3) == 0) {
        // Fast path: copy src/dst rows as int4 (4 edges per op).
        const int4* s4 = (const int4*)ei_raw;
        const int4* t4 = (const int4*)((const int*)ei_raw + E);
        int4* gs4 = (int4*)g_SRC;
        int4* gd4 = (int4*)g_DST;
        const int nv = E >> 2;
        for (int i = gidx; i < nv; i += gstride) {
            gs4[i] = s4[i];
            gd4[i] = t4[i];
        }
        for (int i = E + gidx; i < total; i += gstride) {
            g_SRC[i] = i - E;
            g_DST[i] = i - E;
        }
    } else {
        const long long* ei64 = (const long long*)ei_raw;
        const int*       ei32 = (const int*)ei_raw;
        for (int i = gidx; i < total; i += gstride) {
            int s, d;
            if (i < E) {
                if (is64) { s = (int)ei64[i]; d = (int)ei64[E + i]; }
                else      { s = ei32[i];      d = ei32[E + i]; }
            } else { s = i - E; d = s; }
            g_SRC[i] = s;
            g_DST[i] = d;
        }
    }

    // ---- Loop B: U/P precompute + out init, 4 outputs per thread ----
    const int totalQ = n * 16;
    for (int q = gidx; q < totalQ; q += gstride) {
        int node = q >> 4;
        int k4 = (q & 15) * 4;

        const float4* xr = (const float4*)(x + node * D_FEAT);
        unsigned long long acc01 = pack2f(b1s[k4], b1s[k4 + 1]);
        unsigned long long acc23 = pack2f(b1s[k4 + 2], b1s[k4 + 3]);
#pragma unroll
        for (int f4 = 0; f4 < 8; f4++) {
            float4 xv = xr[f4];
            ulonglong2 w0 = *(const ulonglong2*)&W1s[(f4 * 4 + 0) * 64 + k4];
            ulonglong2 w1 = *(const ulonglong2*)&W1s[(f4 * 4 + 1) * 64 + k4];
            ulonglong2 w2 = *(const ulonglong2*)&W1s[(f4 * 4 + 2) * 64 + k4];
            ulonglong2 w3 = *(const ulonglong2*)&W1s[(f4 * 4 + 3) * 64 + k4];
            unsigned long long xb;
            xb = packdup(xv.x); ffma2(acc01, xb, w0.x); ffma2(acc23, xb, w0.y);
            xb = packdup(xv.y); ffma2(acc01, xb, w1.x); ffma2(acc23, xb, w1.y);
            xb = packdup(xv.z); ffma2(acc01, xb, w2.x); ffma2(acc23, xb, w2.y);
            xb = packdup(xv.w); ffma2(acc01, xb, w3.x); ffma2(acc23, xb, w3.y);
        }
        float px = pos[node * 3 + 0];
        float py = pos[node * 3 + 1];
        float pz = pos[node * 3 + 2];
        ulonglong2 w32 = *(const ulonglong2*)&W1s[32 * 64 + k4];
        ulonglong2 w33 = *(const ulonglong2*)&W1s[33 * 64 + k4];
        ulonglong2 w34 = *(const ulonglong2*)&W1s[34 * 64 + k4];
        unsigned long long pxb = packdup(px);
        unsigned long long pyb = packdup(py);
        unsigned long long pzb = packdup(pz);
        unsigned long long pp01 = mul2(pxb, w32.x);
        unsigned long long pp23 = mul2(pxb, w32.y);
        ffma2(pp01, pyb, w33.x); ffma2(pp23, pyb, w33.y);
        ffma2(pp01, pzb, w34.x); ffma2(pp23, pzb, w34.y);

        unsigned long long u01 = add2(acc01, pp01);
        unsigned long long u23 = add2(acc23, pp23);

        float4 uv, pv;
        unpack2(u01, uv.x, uv.y);
        unpack2(u23, uv.z, uv.w);
        unpack2(pp01, pv.x, pv.y);
        unpack2(pp23, pv.z, pv.w);
        *(float4*)&g_U[node * 64 + k4] = uv;
        *(float4*)&g_P[node * 64 + k4] = pv;
        *(float4*)&out[node * 64 + k4] =
            make_float4(-FLT_MAX, -FLT_MAX, -FLT_MAX, -FLT_MAX);
    }
}

__device__ __forceinline__ void atomicMaxF(float* addr, float v) {
    if (v >= 0.0f) atomicMax((int*)addr, __float_as_int(v));
    else           atomicMin((unsigned int*)addr, __float_as_uint(v));
}

// ---------------------------------------------------------------------------
// Kernel 2: persistent scalar-FFMA2 edge kernel.
// 128 threads/CTA, 6 CTAs/SM, tile = 64 edges x 64 outputs.
// Thread tile = 4 edges x 8 outputs. Edge indices double-buffered in smem
// (prefetched under the epilogue). Bias folded into accumulator init.
// Epilogue: ALL pre-check loads are issued before ANY atomic (batched MLP,
// one exposed L2 latency instead of four serialized ones).
// ---------------------------------------------------------------------------
__global__ void __launch_bounds__(128, 6) edge_kernel(
    const float* __restrict__ W2,       // [64 k][64 n] row-major
    const float* __restrict__ b2,       // [64]
    float* __restrict__ out,            // [n, 64]
    int n, int E) {
    extern __shared__ float smem[];
    float* Hs  = smem;                       // TILE_E * H_STRIDE
    float* W2s = smem + TILE_E * H_STRIDE;   // 64 * 64
    float* b2s = W2s + 64 * 64;              // 64
    // idx double buffer: [2][128] ints; [b][0..63]=src, [b][64..127]=dst(-1=inv)
    int*   ibuf = (int*)(b2s + 64);

    const int tid = threadIdx.x;
    // ---- Stage W2 + b2 once per persistent CTA ----
    for (int i = tid; i < 64 * 64; i += 128) W2s[i] = W2[i];
    if (tid < 64) b2s[tid] = b2[tid];

    const int total = E + n;
    const int nTiles = (total + TILE_E - 1) / TILE_E;

    // ---- Preamble: load idx for first tile into buffer 0 ----
    {
        int t0 = blockIdx.x;
        if (t0 < nTiles) {
            int eg = t0 * TILE_E + (tid & 63);
            int v;
            if (tid < 64) v = (eg < total) ? g_SRC[eg] : 0;
            else          v = (eg < total) ? g_DST[eg] : -1;
            ibuf[tid] = v;
        }
    }
    __syncthreads();

    const int c  = tid & 15;   // float4 chunk of 64-wide row
    const int es = tid >> 4;   // 8 rows per pass
    const int cg = tid & 7;
    const int e0 = tid >> 3;        // 0..15
    const int kb1 = cg * 4;
    const int kb2 = 32 + cg * 4;
    const float4 bbA = *(const float4*)&b2s[kb1];
    const float4 bbB = *(const float4*)&b2s[kb2];
    const unsigned long long bi0 = pack2f(bbA.x, bbA.y);
    const unsigned long long bi1 = pack2f(bbA.z, bbA.w);
    const unsigned long long bi2 = pack2f(bbB.x, bbB.y);
    const unsigned long long bi3 = pack2f(bbB.z, bbB.w);

    int b = 0;
    for (int tile = blockIdx.x; tile < nTiles; tile += gridDim.x, b ^= 1) {
        const int* sbuf = ibuf + b * 128;
        const int* dbuf = sbuf + 64;

        // ---------------- Stage 1: gather + relu into Hs ----------------
#pragma unroll
        for (int j = 0; j < TILE_E / 8; j++) {
            int el = j * 8 + es;
            int d = dbuf[el];
            float4 h = make_float4(0.f, 0.f, 0.f, 0.f);
            if (d >= 0) {
                int s = sbuf[el];
                float4 u = *(const float4*)&g_U[s * 64 + c * 4];
                float4 p = *(const float4*)&g_P[d * 64 + c * 4];
                h.x = fmaxf(u.x - p.x, 0.0f);
                h.y = fmaxf(u.y - p.y, 0.0f);
                h.z = fmaxf(u.z - p.z, 0.0f);
                h.w = fmaxf(u.w - p.w, 0.0f);
                if (c == 0) {
                    prefetchL2(out + d * 64);
                    prefetchL2(out + d * 64 + 32);
                }
            }
            *(float4*)&Hs[el * H_STRIDE + c * 4] = h;
        }
        __syncthreads();

        // ---------------- Stage 2: GEMM (4 edges x 8 cols / thread) -------
        unsigned long long acc[4][4];
#pragma unroll
        for (int i = 0; i < 4; i++) {
            acc[i][0] = bi0; acc[i][1] = bi1; acc[i][2] = bi2; acc[i][3] = bi3;
        }

#pragma unroll
        for (int m4 = 0; m4 < 16; m4++) {
            float h0[4], h1[4], h2[4], h3[4];
            {
                float4 t;
                t = *(const float4*)&Hs[(e0 +  0) * H_STRIDE + m4 * 4];
                h0[0] = t.x; h0[1] = t.y; h0[2] = t.z; h0[3] = t.w;
                t = *(const float4*)&Hs[(e0 + 16) * H_STRIDE + m4 * 4];
                h1[0] = t.x; h1[1] = t.y; h1[2] = t.z; h1[3] = t.w;
                t = *(const float4*)&Hs[(e0 + 32) * H_STRIDE + m4 * 4];
                h2[0] = t.x; h2[1] = t.y; h2[2] = t.z; h2[3] = t.w;
                t = *(const float4*)&Hs[(e0 + 48) * H_STRIDE + m4 * 4];
                h3[0] = t.x; h3[1] = t.y; h3[2] = t.z; h3[3] = t.w;
            }
#pragma unroll
            for (int mm = 0; mm < 4; mm++) {
                const int m = m4 * 4 + mm;
                ulonglong2 wA = *(const ulonglong2*)&W2s[m * 64 + kb1];
                ulonglong2 wB = *(const ulonglong2*)&W2s[m * 64 + kb2];
                unsigned long long hb;
                hb = packdup(h0[mm]);
                ffma2(acc[0][0], hb, wA.x); ffma2(acc[0][1], hb, wA.y);
                ffma2(acc[0][2], hb, wB.x); ffma2(acc[0][3], hb, wB.y);
                hb = packdup(h1[mm]);
                ffma2(acc[1][0], hb, wA.x); ffma2(acc[1][1], hb, wA.y);
                ffma2(acc[1][2], hb, wB.x); ffma2(acc[1][3], hb, wB.y);
                hb = packdup(h2[mm]);
                ffma2(acc[2][0], hb, wA.x); ffma2(acc[2][1], hb, wA.y);
                ffma2(acc[2][2], hb, wB.x); ffma2(acc[2][3], hb, wB.y);
                hb = packdup(h3[mm]);
                ffma2(acc[3][0], hb, wA.x); ffma2(acc[3][1], hb, wA.y);
                ffma2(acc[3][2], hb, wB.x); ffma2(acc[3][3], hb, wB.y);
            }
        }

        // ---- Prefetch next tile's idx (LDG latency hides under epilogue) --
        int nt = tile + gridDim.x;
        int pv = 0;
        bool doPref = (nt < nTiles);
        if (doPref) {
            int eg = nt * TILE_E + (tid & 63);
            if (tid < 64) pv = (eg < total) ? g_SRC[eg] : 0;
            else          pv = (eg < total) ? g_DST[eg] : -1;
        }

        // ---------------- Stage 3: scatter-max (batched pre-check) --------
        // Phase 1: issue ALL pre-check loads (independent, MLP-batched).
        int dd[4];
        float4 curA[4], curB[4];
#pragma unroll
        for (int i = 0; i < 4; i++) {
            dd[i] = dbuf[e0 + 16 * i];
            int dsafe = (dd[i] >= 0) ? dd[i] : 0;
            curA[i] = *(const float4*)(out + dsafe * 64 + kb1);
            curB[i] = *(const float4*)(out + dsafe * 64 + kb2);
        }
        // Phase 2: compares + atomics (no loads between atomics).
#pragma unroll
        for (int i = 0; i < 4; i++) {
            if (dd[i] < 0) continue;
            float v0, v1, v2, v3, v4, v5, v6, v7;
            unpack2(acc[i][0], v0, v1);
            unpack2(acc[i][1], v2, v3);
            unpack2(acc[i][2], v4, v5);
            unpack2(acc[i][3], v6, v7);
            float* oA = out + dd[i] * 64 + kb1;
            float* oB = out + dd[i] * 64 + kb2;
            if (v0 > curA[i].x) atomicMaxF(oA + 0, v0);
            if (v1 > curA[i].y) atomicMaxF(oA + 1, v1);
            if (v2 > curA[i].z) atomicMaxF(oA + 2, v2);
            if (v3 > curA[i].w) atomicMaxF(oA + 3, v3);
            if (v4 > curB[i].x) atomicMaxF(oB + 0, v4);
            if (v5 > curB[i].y) atomicMaxF(oB + 1, v5);
            if (v6 > curB[i].z) atomicMaxF(oB + 2, v6);
            if (v7 > curB[i].w) atomicMaxF(oB + 3, v7);
        }

        // Store prefetched idx into the alternate buffer before the sync.
        if (doPref) ibuf[(b ^ 1) * 128 + tid] = pv;
        __syncthreads();   // Hs + ibuf handoff safe for next tile
    }
}

// ---------------------------------------------------------------------------
// Launch
// ---------------------------------------------------------------------------
extern "C" void kernel_launch(void* const* d_in, const int* in_sizes, int n_in,
                              void* d_out, int out_size) {
    const float* x   = (const float*)d_in[0];    // [n, 32]
    const float* pos = (const float*)d_in[1];    // [n, 3]
    const void*  ei  = d_in[2];                  // [2, E] int64 or int32
    const float* W1  = (const float*)d_in[3];    // [35, 64]
    const float* b1  = (const float*)d_in[4];    // [64]
    const float* W2  = (const float*)d_in[5];    // [64, 64]
    const float* b2  = (const float*)d_in[6];    // [64]
    float*       out = (float*)d_out;            // [n, 64]

    int n = in_sizes[0] / D_FEAT;
    int E = in_sizes[2] / 2;

    const int smemBytes = (TILE_E * H_STRIDE + 64 * 64 + 64) * 4 + 2 * 128 * 4;
    cudaFuncSetAttribute(edge_kernel, cudaFuncAttributeMaxDynamicSharedMemorySize,
                         smemBytes);

    // 1) fused setup: dtype detect + edge normalize + U/P precompute + init
    setup_kernel<<<1480, 256>>>(ei, x, pos, W1, b1, out, E, n);
    // 2) persistent edge kernel: 6 CTAs/SM x 148 SMs
    edge_kernel<<<888, 128, smemBytes>>>(W2, b2, out, n, E);
}